// round 15
// baseline (speedup 1.0000x reference)
#include <cuda_runtime.h>
#include <cuda_bf16.h>
#include <math.h>
#include <stdint.h>

#define Bn 8
#define Ln 1024
#define Dn 1024
#define Hn 16
#define DH 64
#define Mn 8192   // B*L rows

// ---- scratch (no cudaMalloc allowed) ----
__device__ float g_y[(size_t)Mn * Dn];

// activation split planes for query/key/value (3 slots)
__device__ __align__(128) __nv_bfloat16 g_sh[(size_t)3 * Mn * Dn];
__device__ __align__(128) __nv_bfloat16 g_sl[(size_t)3 * Mn * Dn];
// projected Q/K/V hi/lo planes
__device__ __align__(128) __nv_bfloat16 g_qh[(size_t)Mn * Dn];
__device__ __align__(128) __nv_bfloat16 g_ql[(size_t)Mn * Dn];
__device__ __align__(128) __nv_bfloat16 g_kh[(size_t)Mn * Dn];
__device__ __align__(128) __nv_bfloat16 g_kl[(size_t)Mn * Dn];
__device__ __align__(128) __nv_bfloat16 g_vh[(size_t)Mn * Dn];
__device__ __align__(128) __nv_bfloat16 g_vl[(size_t)Mn * Dn];
// context hi/lo
__device__ __align__(128) __nv_bfloat16 g_ch[(size_t)Mn * Dn];
__device__ __align__(128) __nv_bfloat16 g_cl[(size_t)Mn * Dn];
// weight hi/lo planes
__device__ __align__(128) __nv_bfloat16 g_wqh[(size_t)Dn * Dn];
__device__ __align__(128) __nv_bfloat16 g_wql[(size_t)Dn * Dn];
__device__ __align__(128) __nv_bfloat16 g_wkh[(size_t)Dn * Dn];
__device__ __align__(128) __nv_bfloat16 g_wkl[(size_t)Dn * Dn];
__device__ __align__(128) __nv_bfloat16 g_wvh[(size_t)Dn * Dn];
__device__ __align__(128) __nv_bfloat16 g_wvl[(size_t)Dn * Dn];
__device__ __align__(128) __nv_bfloat16 g_woh[(size_t)Dn * Dn];
__device__ __align__(128) __nv_bfloat16 g_wol[(size_t)Dn * Dn];

// ============================================================
// helpers
// ============================================================
__device__ __forceinline__ uint32_t smem_u32(const void* p) {
    uint32_t a;
    asm("{ .reg .u64 t; cvta.to.shared.u64 t, %1; cvt.u32.u64 %0, t; }"
        : "=r"(a) : "l"(p));
    return a;
}
__device__ __forceinline__ void ldm_x4(uint32_t* r, uint32_t addr) {
    asm volatile("ldmatrix.sync.aligned.m8n8.x4.shared.b16 {%0,%1,%2,%3}, [%4];"
                 : "=r"(r[0]), "=r"(r[1]), "=r"(r[2]), "=r"(r[3]) : "r"(addr));
}
__device__ __forceinline__ void ldm_x4t(uint32_t* r, uint32_t addr) {
    asm volatile("ldmatrix.sync.aligned.m8n8.x4.trans.shared.b16 {%0,%1,%2,%3}, [%4];"
                 : "=r"(r[0]), "=r"(r[1]), "=r"(r[2]), "=r"(r[3]) : "r"(addr));
}
__device__ __forceinline__ void mma16816(float* d, const uint32_t* a, const uint32_t* b) {
    asm volatile(
        "mma.sync.aligned.m16n8k16.row.col.f32.bf16.bf16.f32 "
        "{%0,%1,%2,%3}, {%4,%5,%6,%7}, {%8,%9}, {%0,%1,%2,%3};"
        : "+f"(d[0]), "+f"(d[1]), "+f"(d[2]), "+f"(d[3])
        : "r"(a[0]), "r"(a[1]), "r"(a[2]), "r"(a[3]), "r"(b[0]), "r"(b[1]));
}
#define CP16(sa, gp) \
    asm volatile("cp.async.cg.shared.global [%0], [%1], 16;" :: "r"(sa), "l"(gp))
#define CP_COMMIT() asm volatile("cp.async.commit_group;" ::: "memory")
#define CP_WAIT2()  asm volatile("cp.async.wait_group 2;" ::: "memory")
#define CP_WAIT1()  asm volatile("cp.async.wait_group 1;" ::: "memory")
#define CP_WAIT0()  asm volatile("cp.async.wait_group 0;" ::: "memory")

__device__ __forceinline__ uint32_t pack2(__nv_bfloat16 a, __nv_bfloat16 b) {
    return (uint32_t)__bfloat16_as_ushort(a) | ((uint32_t)__bfloat16_as_ushort(b) << 16);
}
__device__ __forceinline__ void split2(float a, float b, uint32_t& hi, uint32_t& lo) {
    __nv_bfloat16 ha = __float2bfloat16_rn(a), hb = __float2bfloat16_rn(b);
    __nv_bfloat16 la = __float2bfloat16_rn(a - __bfloat162float(ha));
    __nv_bfloat16 lb = __float2bfloat16_rn(b - __bfloat162float(hb));
    hi = pack2(ha, hb);
    lo = pack2(la, lb);
}

// ============================================================
// merged splits
// ============================================================
__global__ __launch_bounds__(256) void wsplit_all(
    const float* __restrict__ w0, const float* __restrict__ w1,
    const float* __restrict__ w2, const float* __restrict__ w3,
    __nv_bfloat16* __restrict__ h0, __nv_bfloat16* __restrict__ l0,
    __nv_bfloat16* __restrict__ h1, __nv_bfloat16* __restrict__ l1,
    __nv_bfloat16* __restrict__ h2, __nv_bfloat16* __restrict__ l2,
    __nv_bfloat16* __restrict__ h3, __nv_bfloat16* __restrict__ l3)
{
    int i = blockIdx.x * 256 + threadIdx.x;
    int sel = blockIdx.y;
    const float* in = (sel == 0) ? w0 : (sel == 1) ? w1 : (sel == 2) ? w2 : w3;
    __nv_bfloat16* hi = (sel == 0) ? h0 : (sel == 1) ? h1 : (sel == 2) ? h2 : h3;
    __nv_bfloat16* lo = (sel == 0) ? l0 : (sel == 1) ? l1 : (sel == 2) ? l2 : l3;
    float4 v = ((const float4*)in)[i];
    uint32_t a0, b0, a1, b1;
    split2(v.x, v.y, a0, b0);
    split2(v.z, v.w, a1, b1);
    uint2 hp = {a0, a1}, lp = {b0, b1};
    ((uint2*)hi)[i] = hp;
    ((uint2*)lo)[i] = lp;
}

__global__ __launch_bounds__(256) void asplit3(
    const float* __restrict__ q, const float* __restrict__ k,
    const float* __restrict__ v, __nv_bfloat16* __restrict__ sh,
    __nv_bfloat16* __restrict__ sl)
{
    int i = blockIdx.x * 256 + threadIdx.x;
    int sel = blockIdx.y;
    const float* in = (sel == 0) ? q : (sel == 1) ? k : v;
    size_t off = (size_t)sel * ((size_t)Mn * Dn / 4);
    float4 x = ((const float4*)in)[i];
    uint32_t a0, b0, a1, b1;
    split2(x.x, x.y, a0, b0);
    split2(x.z, x.w, a1, b1);
    uint2 hp = {a0, a1}, lp = {b0, b1};
    ((uint2*)sh)[off + i] = hp;
    ((uint2*)sl)[off + i] = lp;
}

// ============================================================
// HMMA GEMM: acc = sum_k A[m][k]*W[n][k] + bias[n] (+resid)
// CTA 128x128, BK=32, 8 warps, bf16 3-term, 3-stage cp.async.
// ============================================================
#define RS     80u
#define PLANE  10240u
#define STAGE  40960u
#define GM_SMEM (3 * 40960)

__global__ __launch_bounds__(256) void gemm_mma(
    const __nv_bfloat16* __restrict__ Ah, const __nv_bfloat16* __restrict__ Al,
    const __nv_bfloat16* __restrict__ Bh, const __nv_bfloat16* __restrict__ Bl,
    const float* __restrict__ bias, const float* __restrict__ resid,
    float* __restrict__ Cf, __nv_bfloat16* __restrict__ Oh,
    __nv_bfloat16* __restrict__ Ol)
{
    extern __shared__ __align__(128) char sm_raw[];
    const uint32_t base = smem_u32(sm_raw);
    const int tid = threadIdx.x;
    const int lane = tid & 31;
    const int wid = tid >> 5;
    const int m0 = blockIdx.y << 7;
    const int n0 = blockIdx.x << 7;

    const int prow = tid >> 1;
    const int pseg = tid & 1;
    const size_t gA = (size_t)(m0 + prow) * Dn + pseg * 16;
    const size_t gB = (size_t)(n0 + prow) * Dn + pseg * 16;
    const uint32_t so = (uint32_t)prow * RS + (uint32_t)pseg * 32;

    const uint32_t a_off = ((uint32_t)((wid & 1) * 64 + (lane & 15))) * RS
                         + (uint32_t)(lane >> 4) * 16;
    // x4 B fragment: covers both k-steps; rows = n-dim
    const uint32_t b_off = ((uint32_t)((wid >> 1) * 32 + (lane & 7))) * RS
                         + (uint32_t)(lane >> 3) * 16 + 2 * PLANE;

    float acc[4][4][4] = {};

    #pragma unroll
    for (int p = 0; p < 2; p++) {
        uint32_t sb = base + (uint32_t)p * STAGE + so;
        size_t ka = gA + (size_t)p * 32;
        size_t kb = gB + (size_t)p * 32;
        CP16(sb,                 Ah + ka);  CP16(sb + 16,             Ah + ka + 8);
        CP16(sb + PLANE,         Al + ka);  CP16(sb + PLANE + 16,     Al + ka + 8);
        CP16(sb + 2 * PLANE,     Bh + kb);  CP16(sb + 2 * PLANE + 16, Bh + kb + 8);
        CP16(sb + 3 * PLANE,     Bl + kb);  CP16(sb + 3 * PLANE + 16, Bl + kb + 8);
        CP_COMMIT();
    }

    int stage = 0;
    for (int t = 0; t < 32; t++) {
        if (t + 2 < 32) {
            int ns = (t + 2) % 3;
            uint32_t sb = base + (uint32_t)ns * STAGE + so;
            size_t ka = gA + (size_t)(t + 2) * 32;
            size_t kb = gB + (size_t)(t + 2) * 32;
            CP16(sb,                 Ah + ka);  CP16(sb + 16,             Ah + ka + 8);
            CP16(sb + PLANE,         Al + ka);  CP16(sb + PLANE + 16,     Al + ka + 8);
            CP16(sb + 2 * PLANE,     Bh + kb);  CP16(sb + 2 * PLANE + 16, Bh + kb + 8);
            CP16(sb + 3 * PLANE,     Bl + kb);  CP16(sb + 3 * PLANE + 16, Bl + kb + 8);
            CP_COMMIT();
            CP_WAIT2();
        } else if (t + 2 == 32) {
            CP_WAIT1();
        } else {
            CP_WAIT0();
        }
        __syncthreads();

        const uint32_t sb = base + (uint32_t)stage * STAGE;
        stage++; if (stage == 3) stage = 0;

        // B fragments for both k-steps (x4: regs [kk0 f0,f1, kk1 f0,f1])
        uint32_t bh4[4][4], bl4[4][4];
        #pragma unroll
        for (int j = 0; j < 4; j++) {
            uint32_t ba = sb + b_off + (uint32_t)j * (8 * RS);
            ldm_x4(bh4[j], ba);
            ldm_x4(bl4[j], ba + PLANE);
        }

        #pragma unroll
        for (int kk = 0; kk < 2; kk++) {
            uint32_t ah[4][4], al[4][4];
            #pragma unroll
            for (int i = 0; i < 4; i++) {
                uint32_t aa = sb + a_off + (uint32_t)i * (16 * RS) + kk * 32;
                ldm_x4(ah[i], aa);
                ldm_x4(al[i], aa + PLANE);
            }
            #pragma unroll
            for (int i = 0; i < 4; i++)
                #pragma unroll
                for (int j = 0; j < 4; j++) {
                    mma16816(acc[i][j], ah[i], &bh4[j][kk * 2]);
                    mma16816(acc[i][j], ah[i], &bl4[j][kk * 2]);
                    mma16816(acc[i][j], al[i], &bh4[j][kk * 2]);
                }
        }
        __syncthreads();
    }

    // epilogue
    const int rbase = m0 + (wid & 1) * 64 + (lane >> 2);
    const int cbase = n0 + (wid >> 1) * 32 + (lane & 3) * 2;
    #pragma unroll
    for (int i = 0; i < 4; i++) {
        #pragma unroll
        for (int j = 0; j < 4; j++) {
            int rrow = rbase + i * 16;
            int col  = cbase + j * 8;
            float b0 = bias[col], b1 = bias[col + 1];
            float o0 = acc[i][j][0] + b0, o1 = acc[i][j][1] + b1;
            float o2 = acc[i][j][2] + b0, o3 = acc[i][j][3] + b1;
            size_t off0 = (size_t)rrow * Dn + col;
            size_t off1 = (size_t)(rrow + 8) * Dn + col;
            if (resid) {
                float2 r0 = *(const float2*)&resid[off0];
                float2 r1 = *(const float2*)&resid[off1];
                o0 += r0.x; o1 += r0.y; o2 += r1.x; o3 += r1.y;
            }
            if (Cf) {
                float2 w0 = {o0, o1}, w1 = {o2, o3};
                *(float2*)&Cf[off0] = w0;
                *(float2*)&Cf[off1] = w1;
            }
            if (Oh) {
                uint32_t h0, l0, h1, l1;
                split2(o0, o1, h0, l0);
                split2(o2, o3, h1, l1);
                ((uint32_t*)Oh)[off0 >> 1] = h0;
                ((uint32_t*)Ol)[off0 >> 1] = l0;
                ((uint32_t*)Oh)[off1 >> 1] = h1;
                ((uint32_t*)Ol)[off1 >> 1] = l1;
            }
        }
    }
}

// ============================================================
// Tensor-core attention, view-space [128 g][1024][64].
// CTA: 64 q-rows (4 warps x 16), streams 64-key tiles, x4 LDSM.
// ============================================================
#define ARS 144u
#define APL 9216u
#define ASTG 36864u
#define ATT_SMEM (2 * 36864)

__global__ __launch_bounds__(128) void attn_mma(
    const __nv_bfloat16* __restrict__ qh, const __nv_bfloat16* __restrict__ ql,
    const __nv_bfloat16* __restrict__ kh, const __nv_bfloat16* __restrict__ kl,
    const __nv_bfloat16* __restrict__ vh, const __nv_bfloat16* __restrict__ vl,
    const float* __restrict__ qm, const float* __restrict__ km,
    __nv_bfloat16* __restrict__ ch, __nv_bfloat16* __restrict__ cl)
{
    extern __shared__ __align__(128) char asmem[];
    __shared__ float km_s[Ln];
    const uint32_t base = smem_u32(asmem);
    const int tid = threadIdx.x;
    const int lane = tid & 31, wid = tid >> 5;
    const int g = blockIdx.y;
    const int q0 = blockIdx.x << 6;
    const int mb = g & 7;
    const size_t gbase = (size_t)g * (Ln * DH);

    for (int i = tid; i < Ln / 4; i += 128)
        ((float4*)km_s)[i] = ((const float4*)(km + mb * Ln))[i];

    // Q tile into stage-0 smem
    #pragma unroll
    for (int i = 0; i < 8; i++) {
        int id = i * 128 + tid;
        int pl = id >> 9, r = (id >> 3) & 63, seg = id & 7;
        const __nv_bfloat16* src = (pl ? ql : qh) + gbase + (size_t)(q0 + r) * DH + seg * 8;
        CP16(base + (uint32_t)pl * APL + (uint32_t)r * ARS + (uint32_t)seg * 16, src);
    }
    CP_COMMIT();
    CP_WAIT0();
    __syncthreads();

    uint32_t qa_h[4][4], qa_l[4][4];
    {
        uint32_t ab = base + (uint32_t)(wid * 16 + (lane & 15)) * ARS
                    + (uint32_t)(lane >> 4) * 16;
        #pragma unroll
        for (int kb = 0; kb < 4; kb++) {
            ldm_x4(qa_h[kb], ab + kb * 32);
            ldm_x4(qa_l[kb], ab + APL + kb * 32);
        }
    }
    __syncthreads();

    const float qm0 = qm[mb * Ln + q0 + wid * 16 + (lane >> 2)];
    const float qm1 = qm[mb * Ln + q0 + wid * 16 + (lane >> 2) + 8];

    float o[8][4] = {};
    float den0 = 0.f, den1 = 0.f;

    // prologue: K/V tile 0 -> stage 0
    #pragma unroll
    for (int i = 0; i < 16; i++) {
        int id = i * 128 + tid;
        int pl = id >> 9, r = (id >> 3) & 63, seg = id & 7;
        const __nv_bfloat16* bp = (pl == 0) ? kh : (pl == 1) ? kl : (pl == 2) ? vh : vl;
        CP16(base + (uint32_t)pl * APL + (uint32_t)r * ARS + (uint32_t)seg * 16,
             bp + gbase + (size_t)r * DH + seg * 8);
    }
    CP_COMMIT();

    for (int t = 0; t < 16; t++) {
        if (t < 15) {
            uint32_t sb2 = base + (uint32_t)((t + 1) & 1) * ASTG;
            int k0n = (t + 1) << 6;
            #pragma unroll
            for (int i = 0; i < 16; i++) {
                int id = i * 128 + tid;
                int pl = id >> 9, r = (id >> 3) & 63, seg = id & 7;
                const __nv_bfloat16* bp = (pl == 0) ? kh : (pl == 1) ? kl : (pl == 2) ? vh : vl;
                CP16(sb2 + (uint32_t)pl * APL + (uint32_t)r * ARS + (uint32_t)seg * 16,
                     bp + gbase + (size_t)(k0n + r) * DH + seg * 8);
            }
            CP_COMMIT();
            CP_WAIT1();
        } else {
            CP_WAIT0();
        }
        __syncthreads();

        const uint32_t sb = base + (uint32_t)(t & 1) * ASTG;

        // ---- S = Q K^T (3-term), x4 K fragments (2 k-blocks each) ----
        float s[8][4];
        #pragma unroll
        for (int j = 0; j < 8; j++)
            #pragma unroll
            for (int c = 0; c < 4; c++) s[j][c] = 0.f;

        #pragma unroll
        for (int j = 0; j < 8; j++) {
            uint32_t ka = sb + (uint32_t)(j * 8 + (lane & 7)) * ARS
                        + (uint32_t)(lane >> 3) * 16;
            uint32_t kh01[4], kh23[4], kl01[4], kl23[4];
            ldm_x4(kh01, ka);
            ldm_x4(kh23, ka + 64);
            ldm_x4(kl01, ka + APL);
            ldm_x4(kl23, ka + APL + 64);
            mma16816(s[j], qa_h[0], &kh01[0]);
            mma16816(s[j], qa_h[0], &kl01[0]);
            mma16816(s[j], qa_l[0], &kh01[0]);
            mma16816(s[j], qa_h[1], &kh01[2]);
            mma16816(s[j], qa_h[1], &kl01[2]);
            mma16816(s[j], qa_l[1], &kh01[2]);
            mma16816(s[j], qa_h[2], &kh23[0]);
            mma16816(s[j], qa_h[2], &kl23[0]);
            mma16816(s[j], qa_l[2], &kh23[0]);
            mma16816(s[j], qa_h[3], &kh23[2]);
            mma16816(s[j], qa_h[3], &kl23[2]);
            mma16816(s[j], qa_l[3], &kh23[2]);
        }

        // ---- mask + exp + den ----
        float e[8][4];
        const int kcb = (t << 6) + ((lane & 3) << 1);
        #pragma unroll
        for (int j = 0; j < 8; j++) {
            float km0v = km_s[(kcb + j * 8) & (Ln - 1)];
            float km1v = km_s[(kcb + j * 8 + 1) & (Ln - 1)];
            e[j][0] = (qm0 * km0v == 0.f) ? 0.f : __expf(s[j][0] * 0.125f);
            e[j][1] = (qm0 * km1v == 0.f) ? 0.f : __expf(s[j][1] * 0.125f);
            e[j][2] = (qm1 * km0v == 0.f) ? 0.f : __expf(s[j][2] * 0.125f);
            e[j][3] = (qm1 * km1v == 0.f) ? 0.f : __expf(s[j][3] * 0.125f);
            den0 += e[j][0] + e[j][1];
            den1 += e[j][2] + e[j][3];
        }

        // ---- O += P V (3-term), x4 trans V fragments (2 jd each) ----
        const uint32_t vb = sb + 2 * APL + (uint32_t)(lane & 15) * ARS
                          + (uint32_t)(lane >> 4) * 16;
        #pragma unroll
        for (int tt = 0; tt < 4; tt++) {
            uint32_t ah2[4], al2[4];
            split2(e[2 * tt][0],     e[2 * tt][1],     ah2[0], al2[0]);
            split2(e[2 * tt][2],     e[2 * tt][3],     ah2[1], al2[1]);
            split2(e[2 * tt + 1][0], e[2 * tt + 1][1], ah2[2], al2[2]);
            split2(e[2 * tt + 1][2], e[2 * tt + 1][3], ah2[3], al2[3]);
            #pragma unroll
            for (int jd = 0; jd < 8; jd += 2) {
                uint32_t vh4[4], vl4[4];
                uint32_t va = vb + (uint32_t)tt * (16 * ARS) + (uint32_t)jd * 16;
                ldm_x4t(vh4, va);
                ldm_x4t(vl4, va + APL);
                mma16816(o[jd],     ah2, &vh4[0]);
                mma16816(o[jd],     ah2, &vl4[0]);
                mma16816(o[jd],     al2, &vh4[0]);
                mma16816(o[jd + 1], ah2, &vh4[2]);
                mma16816(o[jd + 1], ah2, &vl4[2]);
                mma16816(o[jd + 1], al2, &vh4[2]);
            }
        }
        __syncthreads();
    }

    den0 += __shfl_xor_sync(0xffffffffu, den0, 1);
    den0 += __shfl_xor_sync(0xffffffffu, den0, 2);
    den1 += __shfl_xor_sync(0xffffffffu, den1, 1);
    den1 += __shfl_xor_sync(0xffffffffu, den1, 2);
    const float i0 = 1.f / fmaxf(den0, 2e-15f);
    const float i1 = 1.f / fmaxf(den1, 2e-15f);

    const int row0 = q0 + wid * 16 + (lane >> 2);
    const int colb = (lane & 3) << 1;
    #pragma unroll
    for (int jd = 0; jd < 8; jd++) {
        int col = jd * 8 + colb;
        float v0 = o[jd][0] * i0, v1 = o[jd][1] * i0;
        float v2 = o[jd][2] * i1, v3 = o[jd][3] * i1;
        size_t off0 = gbase + (size_t)row0 * DH + col;
        size_t off1 = off0 + 8 * DH;
        uint32_t h0, l0, h1, l1;
        split2(v0, v1, h0, l0);
        split2(v2, v3, h1, l1);
        ((uint32_t*)ch)[off0 >> 1] = h0;
        ((uint32_t*)cl)[off0 >> 1] = l0;
        ((uint32_t*)ch)[off1 >> 1] = h1;
        ((uint32_t*)cl)[off1 >> 1] = l1;
    }
}

// ============================================================
// LayerNorm
// ============================================================
__global__ __launch_bounds__(256) void ln_kernel(
    const float* __restrict__ y, const float* __restrict__ gamma,
    const float* __restrict__ beta, float* __restrict__ out)
{
    __shared__ float red[8];
    int row = blockIdx.x, tid = threadIdx.x;
    float4 v = ((const float4*)(y + (size_t)row * Dn))[tid];

    float s = v.x + v.y + v.z + v.w;
    #pragma unroll
    for (int o = 16; o; o >>= 1) s += __shfl_xor_sync(0xffffffffu, s, o);
    if ((tid & 31) == 0) red[tid >> 5] = s;
    __syncthreads();
    if (tid < 32) {
        float t = (tid < 8) ? red[tid] : 0.f;
        #pragma unroll
        for (int o = 4; o; o >>= 1) t += __shfl_xor_sync(0xffffffffu, t, o);
        if (tid == 0) red[0] = t;
    }
    __syncthreads();
    float mean = red[0] * (1.f / Dn);
    __syncthreads();

    float dx = v.x - mean, dy = v.y - mean, dz = v.z - mean, dw = v.w - mean;
    float sq = dx * dx + dy * dy + dz * dz + dw * dw;
    #pragma unroll
    for (int o = 16; o; o >>= 1) sq += __shfl_xor_sync(0xffffffffu, sq, o);
    if ((tid & 31) == 0) red[tid >> 5] = sq;
    __syncthreads();
    if (tid < 32) {
        float t = (tid < 8) ? red[tid] : 0.f;
        #pragma unroll
        for (int o = 4; o; o >>= 1) t += __shfl_xor_sync(0xffffffffu, t, o);
        if (tid == 0) red[0] = t;
    }
    __syncthreads();
    float rstd = rsqrtf(red[0] * (1.f / Dn) + 1e-5f);

    float4 g4 = ((const float4*)gamma)[tid];
    float4 b4 = ((const float4*)beta)[tid];
    float4 o4;
    o4.x = dx * rstd * g4.x + b4.x;
    o4.y = dy * rstd * g4.y + b4.y;
    o4.z = dz * rstd * g4.z + b4.z;
    o4.w = dw * rstd * g4.w + b4.w;
    ((float4*)(out + (size_t)row * Dn))[tid] = o4;
}

// ============================================================
extern "C" void kernel_launch(void* const* d_in, const int* in_sizes, int n_in,
                              void* d_out, int out_size)
{
    const float* query  = (const float*)d_in[0];
    const float* key_   = (const float*)d_in[1];
    const float* value  = (const float*)d_in[2];
    const float* q_mask = (const float*)d_in[3];
    const float* k_mask = (const float*)d_in[4];
    const float* Wq = (const float*)d_in[5];
    const float* bq = (const float*)d_in[6];
    const float* Wk = (const float*)d_in[7];
    const float* bk = (const float*)d_in[8];
    const float* Wv = (const float*)d_in[9];
    const float* bv = (const float*)d_in[10];
    const float* Wo = (const float*)d_in[11];
    const float* bo = (const float*)d_in[12];
    const float* gamma = (const float*)d_in[13];
    const float* beta  = (const float*)d_in[14];

    float* y;
    cudaGetSymbolAddress((void**)&y, g_y);

    __nv_bfloat16 *sh, *sl, *qh, *ql, *kh, *kl, *vh, *vl, *ch, *cl;
    __nv_bfloat16 *wqh, *wql, *wkh, *wkl, *wvh, *wvl, *woh, *wol;
    cudaGetSymbolAddress((void**)&sh, g_sh);  cudaGetSymbolAddress((void**)&sl, g_sl);
    cudaGetSymbolAddress((void**)&qh, g_qh);  cudaGetSymbolAddress((void**)&ql, g_ql);
    cudaGetSymbolAddress((void**)&kh, g_kh);  cudaGetSymbolAddress((void**)&kl, g_kl);
    cudaGetSymbolAddress((void**)&vh, g_vh);  cudaGetSymbolAddress((void**)&vl, g_vl);
    cudaGetSymbolAddress((void**)&ch, g_ch);  cudaGetSymbolAddress((void**)&cl, g_cl);
    cudaGetSymbolAddress((void**)&wqh, g_wqh); cudaGetSymbolAddress((void**)&wql, g_wql);
    cudaGetSymbolAddress((void**)&wkh, g_wkh); cudaGetSymbolAddress((void**)&wkl, g_wkl);
    cudaGetSymbolAddress((void**)&wvh, g_wvh); cudaGetSymbolAddress((void**)&wvl, g_wvl);
    cudaGetSymbolAddress((void**)&woh, g_woh); cudaGetSymbolAddress((void**)&wol, g_wol);

    cudaFuncSetAttribute(gemm_mma, cudaFuncAttributeMaxDynamicSharedMemorySize, GM_SMEM);
    cudaFuncSetAttribute(attn_mma, cudaFuncAttributeMaxDynamicSharedMemorySize, ATT_SMEM);

    const int n4_act = (Mn * Dn) / 4;
    const int n4_w   = (Dn * Dn) / 4;
    const size_t actN = (size_t)Mn * Dn;

    // 1: all weight splits in one launch
    wsplit_all<<<dim3(n4_w / 256, 4), 256>>>(Wq, Wk, Wv, Wo,
        wqh, wql, wkh, wkl, wvh, wvl, woh, wol);
    // 2: all activation splits in one launch
    asplit3<<<dim3(n4_act / 256, 3), 256>>>(query, key_, value, sh, sl);

    dim3 gg(Dn / 128, Mn / 128);
    // 3-5: projections
    gemm_mma<<<gg, 256, GM_SMEM>>>(sh,            sl,            wqh, wql, bq, nullptr, nullptr, qh, ql);
    gemm_mma<<<gg, 256, GM_SMEM>>>(sh + actN,     sl + actN,     wkh, wkl, bk, nullptr, nullptr, kh, kl);
    gemm_mma<<<gg, 256, GM_SMEM>>>(sh + 2 * actN, sl + 2 * actN, wvh, wvl, bv, nullptr, nullptr, vh, vl);

    // 6: attention
    attn_mma<<<dim3(Ln / 64, Bn * Hn), 128, ATT_SMEM>>>(
        qh, ql, kh, kl, vh, vl, q_mask, k_mask, ch, cl);

    // 7: output projection + residual
    gemm_mma<<<gg, 256, GM_SMEM>>>(ch, cl, woh, wol, bo, query, y, nullptr, nullptr);

    // 8: layernorm
    ln_kernel<<<Mn, 256>>>(y, gamma, beta, (float*)d_out);
}

// round 16
// speedup vs baseline: 1.1437x; 1.1437x over previous
#include <cuda_runtime.h>
#include <cuda_bf16.h>
#include <math.h>
#include <stdint.h>

#define Bn 8
#define Ln 1024
#define Dn 1024
#define Hn 16
#define DH 64
#define Mn 8192   // B*L rows

// ---- scratch (no cudaMalloc allowed) ----
__device__ float g_y[(size_t)Mn * Dn];

// activation split planes for query/key/value (3 slots)
__device__ __align__(128) __nv_bfloat16 g_sh[(size_t)3 * Mn * Dn];
__device__ __align__(128) __nv_bfloat16 g_sl[(size_t)3 * Mn * Dn];
// projected Q/K/V hi/lo planes
__device__ __align__(128) __nv_bfloat16 g_qh[(size_t)Mn * Dn];
__device__ __align__(128) __nv_bfloat16 g_ql[(size_t)Mn * Dn];
__device__ __align__(128) __nv_bfloat16 g_kh[(size_t)Mn * Dn];
__device__ __align__(128) __nv_bfloat16 g_kl[(size_t)Mn * Dn];
__device__ __align__(128) __nv_bfloat16 g_vh[(size_t)Mn * Dn];
__device__ __align__(128) __nv_bfloat16 g_vl[(size_t)Mn * Dn];
// context hi/lo
__device__ __align__(128) __nv_bfloat16 g_ch[(size_t)Mn * Dn];
__device__ __align__(128) __nv_bfloat16 g_cl[(size_t)Mn * Dn];
// weight hi/lo planes
__device__ __align__(128) __nv_bfloat16 g_wqh[(size_t)Dn * Dn];
__device__ __align__(128) __nv_bfloat16 g_wql[(size_t)Dn * Dn];
__device__ __align__(128) __nv_bfloat16 g_wkh[(size_t)Dn * Dn];
__device__ __align__(128) __nv_bfloat16 g_wkl[(size_t)Dn * Dn];
__device__ __align__(128) __nv_bfloat16 g_wvh[(size_t)Dn * Dn];
__device__ __align__(128) __nv_bfloat16 g_wvl[(size_t)Dn * Dn];
__device__ __align__(128) __nv_bfloat16 g_woh[(size_t)Dn * Dn];
__device__ __align__(128) __nv_bfloat16 g_wol[(size_t)Dn * Dn];

// ============================================================
// helpers
// ============================================================
__device__ __forceinline__ uint32_t smem_u32(const void* p) {
    uint32_t a;
    asm("{ .reg .u64 t; cvta.to.shared.u64 t, %1; cvt.u32.u64 %0, t; }"
        : "=r"(a) : "l"(p));
    return a;
}
__device__ __forceinline__ void ldm_x4(uint32_t* r, uint32_t addr) {
    asm volatile("ldmatrix.sync.aligned.m8n8.x4.shared.b16 {%0,%1,%2,%3}, [%4];"
                 : "=r"(r[0]), "=r"(r[1]), "=r"(r[2]), "=r"(r[3]) : "r"(addr));
}
__device__ __forceinline__ void ldm_x2(uint32_t* r, uint32_t addr) {
    asm volatile("ldmatrix.sync.aligned.m8n8.x2.shared.b16 {%0,%1}, [%2];"
                 : "=r"(r[0]), "=r"(r[1]) : "r"(addr));
}
__device__ __forceinline__ void ldm_x2t(uint32_t* r, uint32_t addr) {
    asm volatile("ldmatrix.sync.aligned.m8n8.x2.trans.shared.b16 {%0,%1}, [%2];"
                 : "=r"(r[0]), "=r"(r[1]) : "r"(addr));
}
__device__ __forceinline__ void mma16816(float* d, const uint32_t* a, const uint32_t* b) {
    asm volatile(
        "mma.sync.aligned.m16n8k16.row.col.f32.bf16.bf16.f32 "
        "{%0,%1,%2,%3}, {%4,%5,%6,%7}, {%8,%9}, {%0,%1,%2,%3};"
        : "+f"(d[0]), "+f"(d[1]), "+f"(d[2]), "+f"(d[3])
        : "r"(a[0]), "r"(a[1]), "r"(a[2]), "r"(a[3]), "r"(b[0]), "r"(b[1]));
}
#define CP16(sa, gp) \
    asm volatile("cp.async.cg.shared.global [%0], [%1], 16;" :: "r"(sa), "l"(gp))
#define CP_COMMIT() asm volatile("cp.async.commit_group;" ::: "memory")
#define CP_WAIT1()  asm volatile("cp.async.wait_group 1;" ::: "memory")
#define CP_WAIT0()  asm volatile("cp.async.wait_group 0;" ::: "memory")

__device__ __forceinline__ uint32_t pack2(__nv_bfloat16 a, __nv_bfloat16 b) {
    return (uint32_t)__bfloat16_as_ushort(a) | ((uint32_t)__bfloat16_as_ushort(b) << 16);
}
__device__ __forceinline__ void split2(float a, float b, uint32_t& hi, uint32_t& lo) {
    __nv_bfloat16 ha = __float2bfloat16_rn(a), hb = __float2bfloat16_rn(b);
    __nv_bfloat16 la = __float2bfloat16_rn(a - __bfloat162float(ha));
    __nv_bfloat16 lb = __float2bfloat16_rn(b - __bfloat162float(hb));
    hi = pack2(ha, hb);
    lo = pack2(la, lb);
}

// ============================================================
// merged splits
// ============================================================
__global__ __launch_bounds__(256) void wsplit_all(
    const float* __restrict__ w0, const float* __restrict__ w1,
    const float* __restrict__ w2, const float* __restrict__ w3,
    __nv_bfloat16* __restrict__ h0, __nv_bfloat16* __restrict__ l0,
    __nv_bfloat16* __restrict__ h1, __nv_bfloat16* __restrict__ l1,
    __nv_bfloat16* __restrict__ h2, __nv_bfloat16* __restrict__ l2,
    __nv_bfloat16* __restrict__ h3, __nv_bfloat16* __restrict__ l3)
{
    int i = blockIdx.x * 256 + threadIdx.x;
    int sel = blockIdx.y;
    const float* in = (sel == 0) ? w0 : (sel == 1) ? w1 : (sel == 2) ? w2 : w3;
    __nv_bfloat16* hi = (sel == 0) ? h0 : (sel == 1) ? h1 : (sel == 2) ? h2 : h3;
    __nv_bfloat16* lo = (sel == 0) ? l0 : (sel == 1) ? l1 : (sel == 2) ? l2 : l3;
    float4 v = ((const float4*)in)[i];
    uint32_t a0, b0, a1, b1;
    split2(v.x, v.y, a0, b0);
    split2(v.z, v.w, a1, b1);
    uint2 hp = {a0, a1}, lp = {b0, b1};
    ((uint2*)hi)[i] = hp;
    ((uint2*)lo)[i] = lp;
}

__global__ __launch_bounds__(256) void asplit3(
    const float* __restrict__ q, const float* __restrict__ k,
    const float* __restrict__ v, __nv_bfloat16* __restrict__ sh,
    __nv_bfloat16* __restrict__ sl)
{
    int i = blockIdx.x * 256 + threadIdx.x;
    int sel = blockIdx.y;
    const float* in = (sel == 0) ? q : (sel == 1) ? k : v;
    size_t off = (size_t)sel * ((size_t)Mn * Dn / 4);
    float4 x = ((const float4*)in)[i];
    uint32_t a0, b0, a1, b1;
    split2(x.x, x.y, a0, b0);
    split2(x.z, x.w, a1, b1);
    uint2 hp = {a0, a1}, lp = {b0, b1};
    ((uint2*)sh)[off + i] = hp;
    ((uint2*)sl)[off + i] = lp;
}

// ============================================================
// HMMA GEMM core: acc = sum_k A[m][k]*W[n][k] + bias[n] (+resid)
// CTA 128x128, BK=32, 8 warps, bf16 3-term, 2-stage cp.async.
// (R11 mainloop; callers add __launch_bounds__(256,2) for 2 CTA/SM)
// ============================================================
#define RS     80u
#define PLANE  10240u
#define STAGE  40960u
#define GM_SMEM (2 * 40960)

__device__ __forceinline__ void gemm_core(
    const __nv_bfloat16* __restrict__ Ah, const __nv_bfloat16* __restrict__ Al,
    const __nv_bfloat16* __restrict__ Bh, const __nv_bfloat16* __restrict__ Bl,
    const float* __restrict__ bias, const float* __restrict__ resid,
    float* __restrict__ Cf, __nv_bfloat16* __restrict__ Oh,
    __nv_bfloat16* __restrict__ Ol, char* dsm)
{
    const uint32_t base = smem_u32(dsm);
    const int tid = threadIdx.x;
    const int lane = tid & 31;
    const int wid = tid >> 5;
    const int m0 = blockIdx.y << 7;
    const int n0 = blockIdx.x << 7;

    const int prow = tid >> 1;
    const int pseg = tid & 1;
    const size_t gA = (size_t)(m0 + prow) * Dn + pseg * 16;
    const size_t gB = (size_t)(n0 + prow) * Dn + pseg * 16;
    const uint32_t so = (uint32_t)prow * RS + (uint32_t)pseg * 32;

    const uint32_t a_off = ((uint32_t)((wid & 1) * 64 + (lane & 15))) * RS
                         + (uint32_t)(lane >> 4) * 16;
    const uint32_t b_off = ((uint32_t)((wid >> 1) * 32 + (lane & 7))) * RS
                         + (uint32_t)((lane >> 3) & 1) * 16 + 2 * PLANE;

    float acc[4][4][4] = {};

    {
        uint32_t sb = base + so;
        CP16(sb,                 Ah + gA);  CP16(sb + 16,             Ah + gA + 8);
        CP16(sb + PLANE,         Al + gA);  CP16(sb + PLANE + 16,     Al + gA + 8);
        CP16(sb + 2 * PLANE,     Bh + gB);  CP16(sb + 2 * PLANE + 16, Bh + gB + 8);
        CP16(sb + 3 * PLANE,     Bl + gB);  CP16(sb + 3 * PLANE + 16, Bl + gB + 8);
        CP_COMMIT();
    }

    for (int t = 0; t < 32; t++) {
        if (t + 1 < 32) {
            uint32_t sb = base + ((t + 1) & 1) * STAGE + so;
            size_t ka = gA + (size_t)(t + 1) * 32;
            size_t kb = gB + (size_t)(t + 1) * 32;
            CP16(sb,                 Ah + ka);  CP16(sb + 16,             Ah + ka + 8);
            CP16(sb + PLANE,         Al + ka);  CP16(sb + PLANE + 16,     Al + ka + 8);
            CP16(sb + 2 * PLANE,     Bh + kb);  CP16(sb + 2 * PLANE + 16, Bh + kb + 8);
            CP16(sb + 3 * PLANE,     Bl + kb);  CP16(sb + 3 * PLANE + 16, Bl + kb + 8);
            CP_COMMIT();
            CP_WAIT1();
        } else {
            CP_WAIT0();
        }
        __syncthreads();

        const uint32_t sb = base + (t & 1) * STAGE;
        #pragma unroll
        for (int kk = 0; kk < 32; kk += 16) {
            uint32_t ah[4][4], al[4][4], bh[4][2], bl[4][2];
            #pragma unroll
            for (int i = 0; i < 4; i++)
                ldm_x4(ah[i], sb + a_off + (uint32_t)i * (16 * RS) + kk * 2);
            #pragma unroll
            for (int i = 0; i < 4; i++)
                ldm_x4(al[i], sb + PLANE + a_off + (uint32_t)i * (16 * RS) + kk * 2);
            #pragma unroll
            for (int j = 0; j < 4; j++)
                ldm_x2(bh[j], sb + b_off + (uint32_t)j * (8 * RS) + kk * 2);
            #pragma unroll
            for (int j = 0; j < 4; j++)
                ldm_x2(bl[j], sb + PLANE + b_off + (uint32_t)j * (8 * RS) + kk * 2);

            #pragma unroll
            for (int i = 0; i < 4; i++)
                #pragma unroll
                for (int j = 0; j < 4; j++) {
                    mma16816(acc[i][j], ah[i], bh[j]);
                    mma16816(acc[i][j], ah[i], bl[j]);
                    mma16816(acc[i][j], al[i], bh[j]);
                }
        }
        __syncthreads();
    }

    // epilogue
    const int rbase = m0 + (wid & 1) * 64 + (lane >> 2);
    const int cbase = n0 + (wid >> 1) * 32 + (lane & 3) * 2;
    #pragma unroll
    for (int i = 0; i < 4; i++) {
        #pragma unroll
        for (int j = 0; j < 4; j++) {
            int rrow = rbase + i * 16;
            int col  = cbase + j * 8;
            float b0 = bias[col], b1 = bias[col + 1];
            float o0 = acc[i][j][0] + b0, o1 = acc[i][j][1] + b1;
            float o2 = acc[i][j][2] + b0, o3 = acc[i][j][3] + b1;
            size_t off0 = (size_t)rrow * Dn + col;
            size_t off1 = (size_t)(rrow + 8) * Dn + col;
            if (resid) {
                float2 r0 = *(const float2*)&resid[off0];
                float2 r1 = *(const float2*)&resid[off1];
                o0 += r0.x; o1 += r0.y; o2 += r1.x; o3 += r1.y;
            }
            if (Cf) {
                float2 w0 = {o0, o1}, w1 = {o2, o3};
                *(float2*)&Cf[off0] = w0;
                *(float2*)&Cf[off1] = w1;
            }
            if (Oh) {
                uint32_t h0, l0, h1, l1;
                split2(o0, o1, h0, l0);
                split2(o2, o3, h1, l1);
                ((uint32_t*)Oh)[off0 >> 1] = h0;
                ((uint32_t*)Ol)[off0 >> 1] = l0;
                ((uint32_t*)Oh)[off1 >> 1] = h1;
                ((uint32_t*)Ol)[off1 >> 1] = l1;
            }
        }
    }
}

// merged Q/K/V projections: blockIdx.z selects which
__global__ __launch_bounds__(256, 2) void qkv_gemm(
    const __nv_bfloat16* __restrict__ sh, const __nv_bfloat16* __restrict__ sl,
    const __nv_bfloat16* __restrict__ wqh, const __nv_bfloat16* __restrict__ wql,
    const __nv_bfloat16* __restrict__ wkh, const __nv_bfloat16* __restrict__ wkl,
    const __nv_bfloat16* __restrict__ wvh, const __nv_bfloat16* __restrict__ wvl,
    const float* __restrict__ bq, const float* __restrict__ bk,
    const float* __restrict__ bv,
    __nv_bfloat16* __restrict__ qh, __nv_bfloat16* __restrict__ ql,
    __nv_bfloat16* __restrict__ kh, __nv_bfloat16* __restrict__ kl,
    __nv_bfloat16* __restrict__ vh, __nv_bfloat16* __restrict__ vl)
{
    extern __shared__ __align__(128) char dsm[];
    const int z = blockIdx.z;
    const size_t actN = (size_t)Mn * Dn;
    const __nv_bfloat16* Ah = sh + (size_t)z * actN;
    const __nv_bfloat16* Al = sl + (size_t)z * actN;
    const __nv_bfloat16* Bh = (z == 0) ? wqh : (z == 1) ? wkh : wvh;
    const __nv_bfloat16* Bl = (z == 0) ? wql : (z == 1) ? wkl : wvl;
    const float* bias = (z == 0) ? bq : (z == 1) ? bk : bv;
    __nv_bfloat16* Oh = (z == 0) ? qh : (z == 1) ? kh : vh;
    __nv_bfloat16* Ol = (z == 0) ? ql : (z == 1) ? kl : vl;
    gemm_core(Ah, Al, Bh, Bl, bias, nullptr, nullptr, Oh, Ol, dsm);
}

// output projection + residual -> fp32
__global__ __launch_bounds__(256, 2) void o_gemm(
    const __nv_bfloat16* __restrict__ ch, const __nv_bfloat16* __restrict__ cl,
    const __nv_bfloat16* __restrict__ woh, const __nv_bfloat16* __restrict__ wol,
    const float* __restrict__ bo, const float* __restrict__ resid,
    float* __restrict__ y)
{
    extern __shared__ __align__(128) char dsm[];
    gemm_core(ch, cl, woh, wol, bo, resid, y, nullptr, nullptr, dsm);
}

// ============================================================
// Tensor-core attention (R11 form), view-space [128 g][1024][64].
// CTA: 64 q-rows (4 warps x 16), streams 64-key tiles.
// ============================================================
#define ARS 144u
#define APL 9216u
#define ASTG 36864u
#define ATT_SMEM (2 * 36864)

__global__ __launch_bounds__(128) void attn_mma(
    const __nv_bfloat16* __restrict__ qh, const __nv_bfloat16* __restrict__ ql,
    const __nv_bfloat16* __restrict__ kh, const __nv_bfloat16* __restrict__ kl,
    const __nv_bfloat16* __restrict__ vh, const __nv_bfloat16* __restrict__ vl,
    const float* __restrict__ qm, const float* __restrict__ km,
    __nv_bfloat16* __restrict__ ch, __nv_bfloat16* __restrict__ cl)
{
    extern __shared__ __align__(128) char asmem[];
    __shared__ float km_s[Ln];
    const uint32_t base = smem_u32(asmem);
    const int tid = threadIdx.x;
    const int lane = tid & 31, wid = tid >> 5;
    const int g = blockIdx.y;
    const int q0 = blockIdx.x << 6;
    const int mb = g & 7;
    const size_t gbase = (size_t)g * (Ln * DH);

    for (int i = tid; i < Ln / 4; i += 128)
        ((float4*)km_s)[i] = ((const float4*)(km + mb * Ln))[i];

    // Q tile into stage-0 smem
    #pragma unroll
    for (int i = 0; i < 8; i++) {
        int id = i * 128 + tid;
        int pl = id >> 9, r = (id >> 3) & 63, seg = id & 7;
        const __nv_bfloat16* src = (pl ? ql : qh) + gbase + (size_t)(q0 + r) * DH + seg * 8;
        CP16(base + (uint32_t)pl * APL + (uint32_t)r * ARS + (uint32_t)seg * 16, src);
    }
    CP_COMMIT();
    CP_WAIT0();
    __syncthreads();

    uint32_t qa_h[4][4], qa_l[4][4];
    {
        uint32_t ab = base + (uint32_t)(wid * 16 + (lane & 15)) * ARS
                    + (uint32_t)(lane >> 4) * 16;
        #pragma unroll
        for (int kb = 0; kb < 4; kb++) {
            ldm_x4(qa_h[kb], ab + kb * 32);
            ldm_x4(qa_l[kb], ab + APL + kb * 32);
        }
    }
    __syncthreads();

    const float qm0 = qm[mb * Ln + q0 + wid * 16 + (lane >> 2)];
    const float qm1 = qm[mb * Ln + q0 + wid * 16 + (lane >> 2) + 8];

    float o[8][4] = {};
    float den0 = 0.f, den1 = 0.f;

    // prologue: K/V tile 0 -> stage 0
    #pragma unroll
    for (int i = 0; i < 16; i++) {
        int id = i * 128 + tid;
        int pl = id >> 9, r = (id >> 3) & 63, seg = id & 7;
        const __nv_bfloat16* bp = (pl == 0) ? kh : (pl == 1) ? kl : (pl == 2) ? vh : vl;
        CP16(base + (uint32_t)pl * APL + (uint32_t)r * ARS + (uint32_t)seg * 16,
             bp + gbase + (size_t)r * DH + seg * 8);
    }
    CP_COMMIT();

    for (int t = 0; t < 16; t++) {
        if (t < 15) {
            uint32_t sb2 = base + (uint32_t)((t + 1) & 1) * ASTG;
            int k0n = (t + 1) << 6;
            #pragma unroll
            for (int i = 0; i < 16; i++) {
                int id = i * 128 + tid;
                int pl = id >> 9, r = (id >> 3) & 63, seg = id & 7;
                const __nv_bfloat16* bp = (pl == 0) ? kh : (pl == 1) ? kl : (pl == 2) ? vh : vl;
                CP16(sb2 + (uint32_t)pl * APL + (uint32_t)r * ARS + (uint32_t)seg * 16,
                     bp + gbase + (size_t)(k0n + r) * DH + seg * 8);
            }
            CP_COMMIT();
            CP_WAIT1();
        } else {
            CP_WAIT0();
        }
        __syncthreads();

        const uint32_t sb = base + (uint32_t)(t & 1) * ASTG;

        // ---- S = Q K^T (3-term) ----
        float s[8][4];
        #pragma unroll
        for (int j = 0; j < 8; j++)
            #pragma unroll
            for (int c = 0; c < 4; c++) s[j][c] = 0.f;

        const uint32_t bb = sb + (uint32_t)(lane & 7) * ARS
                          + (uint32_t)((lane >> 3) & 1) * 16;
        #pragma unroll
        for (int j = 0; j < 8; j++) {
            #pragma unroll
            for (int kb = 0; kb < 4; kb++) {
                uint32_t bh2[2], bl2[2];
                ldm_x2(bh2, bb + (uint32_t)j * (8 * ARS) + kb * 32);
                ldm_x2(bl2, bb + APL + (uint32_t)j * (8 * ARS) + kb * 32);
                mma16816(s[j], qa_h[kb], bh2);
                mma16816(s[j], qa_h[kb], bl2);
                mma16816(s[j], qa_l[kb], bh2);
            }
        }

        // ---- mask + exp + den ----
        float e[8][4];
        const int kcb = (t << 6) + ((lane & 3) << 1);
        #pragma unroll
        for (int j = 0; j < 8; j++) {
            float km0v = km_s[(kcb + j * 8) & (Ln - 1)];
            float km1v = km_s[(kcb + j * 8 + 1) & (Ln - 1)];
            e[j][0] = (qm0 * km0v == 0.f) ? 0.f : __expf(s[j][0] * 0.125f);
            e[j][1] = (qm0 * km1v == 0.f) ? 0.f : __expf(s[j][1] * 0.125f);
            e[j][2] = (qm1 * km0v == 0.f) ? 0.f : __expf(s[j][2] * 0.125f);
            e[j][3] = (qm1 * km1v == 0.f) ? 0.f : __expf(s[j][3] * 0.125f);
            den0 += e[j][0] + e[j][1];
            den1 += e[j][2] + e[j][3];
        }

        // ---- O += P V (3-term, P split in regs) ----
        const uint32_t vb = sb + 2 * APL + (uint32_t)(lane & 15) * ARS;
        #pragma unroll
        for (int tt = 0; tt < 4; tt++) {
            uint32_t ah2[4], al2[4];
            split2(e[2 * tt][0],     e[2 * tt][1],     ah2[0], al2[0]);
            split2(e[2 * tt][2],     e[2 * tt][3],     ah2[1], al2[1]);
            split2(e[2 * tt + 1][0], e[2 * tt + 1][1], ah2[2], al2[2]);
            split2(e[2 * tt + 1][2], e[2 * tt + 1][3], ah2[3], al2[3]);
            #pragma unroll
            for (int jd = 0; jd < 8; jd++) {
                uint32_t vh2[2], vl2[2];
                ldm_x2t(vh2, vb + (uint32_t)tt * (16 * ARS) + jd * 16);
                ldm_x2t(vl2, vb + APL + (uint32_t)tt * (16 * ARS) + jd * 16);
                mma16816(o[jd], ah2, vh2);
                mma16816(o[jd], ah2, vl2);
                mma16816(o[jd], al2, vh2);
            }
        }
        __syncthreads();
    }

    den0 += __shfl_xor_sync(0xffffffffu, den0, 1);
    den0 += __shfl_xor_sync(0xffffffffu, den0, 2);
    den1 += __shfl_xor_sync(0xffffffffu, den1, 1);
    den1 += __shfl_xor_sync(0xffffffffu, den1, 2);
    const float i0 = 1.f / fmaxf(den0, 2e-15f);
    const float i1 = 1.f / fmaxf(den1, 2e-15f);

    const int row0 = q0 + wid * 16 + (lane >> 2);
    const int colb = (lane & 3) << 1;
    #pragma unroll
    for (int jd = 0; jd < 8; jd++) {
        int col = jd * 8 + colb;
        float v0 = o[jd][0] * i0, v1 = o[jd][1] * i0;
        float v2 = o[jd][2] * i1, v3 = o[jd][3] * i1;
        size_t off0 = gbase + (size_t)row0 * DH + col;
        size_t off1 = off0 + 8 * DH;
        uint32_t h0, l0, h1, l1;
        split2(v0, v1, h0, l0);
        split2(v2, v3, h1, l1);
        ((uint32_t*)ch)[off0 >> 1] = h0;
        ((uint32_t*)cl)[off0 >> 1] = l0;
        ((uint32_t*)ch)[off1 >> 1] = h1;
        ((uint32_t*)cl)[off1 >> 1] = l1;
    }
}

// ============================================================
// LayerNorm
// ============================================================
__global__ __launch_bounds__(256) void ln_kernel(
    const float* __restrict__ y, const float* __restrict__ gamma,
    const float* __restrict__ beta, float* __restrict__ out)
{
    __shared__ float red[8];
    int row = blockIdx.x, tid = threadIdx.x;
    float4 v = ((const float4*)(y + (size_t)row * Dn))[tid];

    float s = v.x + v.y + v.z + v.w;
    #pragma unroll
    for (int o = 16; o; o >>= 1) s += __shfl_xor_sync(0xffffffffu, s, o);
    if ((tid & 31) == 0) red[tid >> 5] = s;
    __syncthreads();
    if (tid < 32) {
        float t = (tid < 8) ? red[tid] : 0.f;
        #pragma unroll
        for (int o = 4; o; o >>= 1) t += __shfl_xor_sync(0xffffffffu, t, o);
        if (tid == 0) red[0] = t;
    }
    __syncthreads();
    float mean = red[0] * (1.f / Dn);
    __syncthreads();

    float dx = v.x - mean, dy = v.y - mean, dz = v.z - mean, dw = v.w - mean;
    float sq = dx * dx + dy * dy + dz * dz + dw * dw;
    #pragma unroll
    for (int o = 16; o; o >>= 1) sq += __shfl_xor_sync(0xffffffffu, sq, o);
    if ((tid & 31) == 0) red[tid >> 5] = sq;
    __syncthreads();
    if (tid < 32) {
        float t = (tid < 8) ? red[tid] : 0.f;
        #pragma unroll
        for (int o = 4; o; o >>= 1) t += __shfl_xor_sync(0xffffffffu, t, o);
        if (tid == 0) red[0] = t;
    }
    __syncthreads();
    float rstd = rsqrtf(red[0] * (1.f / Dn) + 1e-5f);

    float4 g4 = ((const float4*)gamma)[tid];
    float4 b4 = ((const float4*)beta)[tid];
    float4 o4;
    o4.x = dx * rstd * g4.x + b4.x;
    o4.y = dy * rstd * g4.y + b4.y;
    o4.z = dz * rstd * g4.z + b4.z;
    o4.w = dw * rstd * g4.w + b4.w;
    ((float4*)(out + (size_t)row * Dn))[tid] = o4;
}

// ============================================================
extern "C" void kernel_launch(void* const* d_in, const int* in_sizes, int n_in,
                              void* d_out, int out_size)
{
    const float* query  = (const float*)d_in[0];
    const float* key_   = (const float*)d_in[1];
    const float* value  = (const float*)d_in[2];
    const float* q_mask = (const float*)d_in[3];
    const float* k_mask = (const float*)d_in[4];
    const float* Wq = (const float*)d_in[5];
    const float* bq = (const float*)d_in[6];
    const float* Wk = (const float*)d_in[7];
    const float* bk = (const float*)d_in[8];
    const float* Wv = (const float*)d_in[9];
    const float* bv = (const float*)d_in[10];
    const float* Wo = (const float*)d_in[11];
    const float* bo = (const float*)d_in[12];
    const float* gamma = (const float*)d_in[13];
    const float* beta  = (const float*)d_in[14];

    float* y;
    cudaGetSymbolAddress((void**)&y, g_y);

    __nv_bfloat16 *sh, *sl, *qh, *ql, *kh, *kl, *vh, *vl, *ch, *cl;
    __nv_bfloat16 *wqh, *wql, *wkh, *wkl, *wvh, *wvl, *woh, *wol;
    cudaGetSymbolAddress((void**)&sh, g_sh);  cudaGetSymbolAddress((void**)&sl, g_sl);
    cudaGetSymbolAddress((void**)&qh, g_qh);  cudaGetSymbolAddress((void**)&ql, g_ql);
    cudaGetSymbolAddress((void**)&kh, g_kh);  cudaGetSymbolAddress((void**)&kl, g_kl);
    cudaGetSymbolAddress((void**)&vh, g_vh);  cudaGetSymbolAddress((void**)&vl, g_vl);
    cudaGetSymbolAddress((void**)&ch, g_ch);  cudaGetSymbolAddress((void**)&cl, g_cl);
    cudaGetSymbolAddress((void**)&wqh, g_wqh); cudaGetSymbolAddress((void**)&wql, g_wql);
    cudaGetSymbolAddress((void**)&wkh, g_wkh); cudaGetSymbolAddress((void**)&wkl, g_wkl);
    cudaGetSymbolAddress((void**)&wvh, g_wvh); cudaGetSymbolAddress((void**)&wvl, g_wvl);
    cudaGetSymbolAddress((void**)&woh, g_woh); cudaGetSymbolAddress((void**)&wol, g_wol);

    cudaFuncSetAttribute(qkv_gemm, cudaFuncAttributeMaxDynamicSharedMemorySize, GM_SMEM);
    cudaFuncSetAttribute(o_gemm,   cudaFuncAttributeMaxDynamicSharedMemorySize, GM_SMEM);
    cudaFuncSetAttribute(attn_mma, cudaFuncAttributeMaxDynamicSharedMemorySize, ATT_SMEM);

    const int n4_act = (Mn * Dn) / 4;
    const int n4_w   = (Dn * Dn) / 4;

    // 1: all weight splits
    wsplit_all<<<dim3(n4_w / 256, 4), 256>>>(Wq, Wk, Wv, Wo,
        wqh, wql, wkh, wkl, wvh, wvl, woh, wol);
    // 2: all activation splits
    asplit3<<<dim3(n4_act / 256, 3), 256>>>(query, key_, value, sh, sl);

    // 3: merged Q/K/V projections
    qkv_gemm<<<dim3(Dn / 128, Mn / 128, 3), 256, GM_SMEM>>>(
        sh, sl, wqh, wql, wkh, wkl, wvh, wvl, bq, bk, bv,
        qh, ql, kh, kl, vh, vl);

    // 4: attention
    attn_mma<<<dim3(Ln / 64, Bn * Hn), 128, ATT_SMEM>>>(
        qh, ql, kh, kl, vh, vl, q_mask, k_mask, ch, cl);

    // 5: output projection + residual
    o_gemm<<<dim3(Dn / 128, Mn / 128), 256, GM_SMEM>>>(
        ch, cl, woh, wol, bo, query, y);

    // 6: layernorm
    ln_kernel<<<Mn, 256>>>(y, gamma, beta, (float*)d_out);
}

// round 17
// speedup vs baseline: 1.2634x; 1.1047x over previous
#include <cuda_runtime.h>
#include <cuda_bf16.h>
#include <math.h>
#include <stdint.h>

#define Bn 8
#define Ln 1024
#define Dn 1024
#define Hn 16
#define DH 64
#define Mn 8192   // B*L rows

// ---- scratch (no cudaMalloc allowed) ----
__device__ float g_y[(size_t)Mn * Dn];

// activation split planes for query/key/value (3 slots)
__device__ __align__(128) __nv_bfloat16 g_sh[(size_t)3 * Mn * Dn];
__device__ __align__(128) __nv_bfloat16 g_sl[(size_t)3 * Mn * Dn];
// projected Q/K/V hi/lo planes
__device__ __align__(128) __nv_bfloat16 g_qh[(size_t)Mn * Dn];
__device__ __align__(128) __nv_bfloat16 g_ql[(size_t)Mn * Dn];
__device__ __align__(128) __nv_bfloat16 g_kh[(size_t)Mn * Dn];
__device__ __align__(128) __nv_bfloat16 g_kl[(size_t)Mn * Dn];
__device__ __align__(128) __nv_bfloat16 g_vh[(size_t)Mn * Dn];
__device__ __align__(128) __nv_bfloat16 g_vl[(size_t)Mn * Dn];
// context hi/lo
__device__ __align__(128) __nv_bfloat16 g_ch[(size_t)Mn * Dn];
__device__ __align__(128) __nv_bfloat16 g_cl[(size_t)Mn * Dn];
// weight hi/lo planes
__device__ __align__(128) __nv_bfloat16 g_wqh[(size_t)Dn * Dn];
__device__ __align__(128) __nv_bfloat16 g_wql[(size_t)Dn * Dn];
__device__ __align__(128) __nv_bfloat16 g_wkh[(size_t)Dn * Dn];
__device__ __align__(128) __nv_bfloat16 g_wkl[(size_t)Dn * Dn];
__device__ __align__(128) __nv_bfloat16 g_wvh[(size_t)Dn * Dn];
__device__ __align__(128) __nv_bfloat16 g_wvl[(size_t)Dn * Dn];
__device__ __align__(128) __nv_bfloat16 g_woh[(size_t)Dn * Dn];
__device__ __align__(128) __nv_bfloat16 g_wol[(size_t)Dn * Dn];

// ============================================================
// helpers
// ============================================================
__device__ __forceinline__ uint32_t smem_u32(const void* p) {
    uint32_t a;
    asm("{ .reg .u64 t; cvta.to.shared.u64 t, %1; cvt.u32.u64 %0, t; }"
        : "=r"(a) : "l"(p));
    return a;
}
__device__ __forceinline__ void ldm_x4(uint32_t* r, uint32_t addr) {
    asm volatile("ldmatrix.sync.aligned.m8n8.x4.shared.b16 {%0,%1,%2,%3}, [%4];"
                 : "=r"(r[0]), "=r"(r[1]), "=r"(r[2]), "=r"(r[3]) : "r"(addr));
}
__device__ __forceinline__ void ldm_x2(uint32_t* r, uint32_t addr) {
    asm volatile("ldmatrix.sync.aligned.m8n8.x2.shared.b16 {%0,%1}, [%2];"
                 : "=r"(r[0]), "=r"(r[1]) : "r"(addr));
}
__device__ __forceinline__ void ldm_x2t(uint32_t* r, uint32_t addr) {
    asm volatile("ldmatrix.sync.aligned.m8n8.x2.trans.shared.b16 {%0,%1}, [%2];"
                 : "=r"(r[0]), "=r"(r[1]) : "r"(addr));
}
__device__ __forceinline__ void mma16816(float* d, const uint32_t* a, const uint32_t* b) {
    asm volatile(
        "mma.sync.aligned.m16n8k16.row.col.f32.bf16.bf16.f32 "
        "{%0,%1,%2,%3}, {%4,%5,%6,%7}, {%8,%9}, {%0,%1,%2,%3};"
        : "+f"(d[0]), "+f"(d[1]), "+f"(d[2]), "+f"(d[3])
        : "r"(a[0]), "r"(a[1]), "r"(a[2]), "r"(a[3]), "r"(b[0]), "r"(b[1]));
}
#define CP16(sa, gp) \
    asm volatile("cp.async.cg.shared.global [%0], [%1], 16;" :: "r"(sa), "l"(gp))
#define CP_COMMIT() asm volatile("cp.async.commit_group;" ::: "memory")
#define CP_WAIT1()  asm volatile("cp.async.wait_group 1;" ::: "memory")
#define CP_WAIT0()  asm volatile("cp.async.wait_group 0;" ::: "memory")

__device__ __forceinline__ uint32_t pack2(__nv_bfloat16 a, __nv_bfloat16 b) {
    return (uint32_t)__bfloat16_as_ushort(a) | ((uint32_t)__bfloat16_as_ushort(b) << 16);
}
__device__ __forceinline__ void split2(float a, float b, uint32_t& hi, uint32_t& lo) {
    __nv_bfloat16 ha = __float2bfloat16_rn(a), hb = __float2bfloat16_rn(b);
    __nv_bfloat16 la = __float2bfloat16_rn(a - __bfloat162float(ha));
    __nv_bfloat16 lb = __float2bfloat16_rn(b - __bfloat162float(hb));
    hi = pack2(ha, hb);
    lo = pack2(la, lb);
}

// ============================================================
// merged splits
// ============================================================
__global__ __launch_bounds__(256) void wsplit_all(
    const float* __restrict__ w0, const float* __restrict__ w1,
    const float* __restrict__ w2, const float* __restrict__ w3,
    __nv_bfloat16* __restrict__ h0, __nv_bfloat16* __restrict__ l0,
    __nv_bfloat16* __restrict__ h1, __nv_bfloat16* __restrict__ l1,
    __nv_bfloat16* __restrict__ h2, __nv_bfloat16* __restrict__ l2,
    __nv_bfloat16* __restrict__ h3, __nv_bfloat16* __restrict__ l3)
{
    int i = blockIdx.x * 256 + threadIdx.x;
    int sel = blockIdx.y;
    const float* in = (sel == 0) ? w0 : (sel == 1) ? w1 : (sel == 2) ? w2 : w3;
    __nv_bfloat16* hi = (sel == 0) ? h0 : (sel == 1) ? h1 : (sel == 2) ? h2 : h3;
    __nv_bfloat16* lo = (sel == 0) ? l0 : (sel == 1) ? l1 : (sel == 2) ? l2 : l3;
    float4 v = ((const float4*)in)[i];
    uint32_t a0, b0, a1, b1;
    split2(v.x, v.y, a0, b0);
    split2(v.z, v.w, a1, b1);
    uint2 hp = {a0, a1}, lp = {b0, b1};
    ((uint2*)hi)[i] = hp;
    ((uint2*)lo)[i] = lp;
}

__global__ __launch_bounds__(256) void asplit3(
    const float* __restrict__ q, const float* __restrict__ k,
    const float* __restrict__ v, __nv_bfloat16* __restrict__ sh,
    __nv_bfloat16* __restrict__ sl)
{
    int i = blockIdx.x * 256 + threadIdx.x;
    int sel = blockIdx.y;
    const float* in = (sel == 0) ? q : (sel == 1) ? k : v;
    size_t off = (size_t)sel * ((size_t)Mn * Dn / 4);
    float4 x = ((const float4*)in)[i];
    uint32_t a0, b0, a1, b1;
    split2(x.x, x.y, a0, b0);
    split2(x.z, x.w, a1, b1);
    uint2 hp = {a0, a1}, lp = {b0, b1};
    ((uint2*)sh)[off + i] = hp;
    ((uint2*)sl)[off + i] = lp;
}

// ============================================================
// HMMA GEMM core: acc = sum_k A[m][k]*W[n][k] + bias[n] (+resid)
// CTA 128x128, BK=32, 8 warps, bf16 3-term, 2-stage cp.async.
// ============================================================
#define RS     80u
#define PLANE  10240u
#define STAGE  40960u
#define GM_SMEM (2 * 40960)

__device__ __forceinline__ void gemm_core(
    const __nv_bfloat16* __restrict__ Ah, const __nv_bfloat16* __restrict__ Al,
    const __nv_bfloat16* __restrict__ Bh, const __nv_bfloat16* __restrict__ Bl,
    const float* __restrict__ bias, const float* __restrict__ resid,
    float* __restrict__ Cf, __nv_bfloat16* __restrict__ Oh,
    __nv_bfloat16* __restrict__ Ol, char* dsm)
{
    const uint32_t base = smem_u32(dsm);
    const int tid = threadIdx.x;
    const int lane = tid & 31;
    const int wid = tid >> 5;
    const int m0 = blockIdx.y << 7;
    const int n0 = blockIdx.x << 7;

    const int prow = tid >> 1;
    const int pseg = tid & 1;
    const size_t gA = (size_t)(m0 + prow) * Dn + pseg * 16;
    const size_t gB = (size_t)(n0 + prow) * Dn + pseg * 16;
    const uint32_t so = (uint32_t)prow * RS + (uint32_t)pseg * 32;

    const uint32_t a_off = ((uint32_t)((wid & 1) * 64 + (lane & 15))) * RS
                         + (uint32_t)(lane >> 4) * 16;
    const uint32_t b_off = ((uint32_t)((wid >> 1) * 32 + (lane & 7))) * RS
                         + (uint32_t)((lane >> 3) & 1) * 16 + 2 * PLANE;

    float acc[4][4][4] = {};

    {
        uint32_t sb = base + so;
        CP16(sb,                 Ah + gA);  CP16(sb + 16,             Ah + gA + 8);
        CP16(sb + PLANE,         Al + gA);  CP16(sb + PLANE + 16,     Al + gA + 8);
        CP16(sb + 2 * PLANE,     Bh + gB);  CP16(sb + 2 * PLANE + 16, Bh + gB + 8);
        CP16(sb + 3 * PLANE,     Bl + gB);  CP16(sb + 3 * PLANE + 16, Bl + gB + 8);
        CP_COMMIT();
    }

    for (int t = 0; t < 32; t++) {
        if (t + 1 < 32) {
            uint32_t sb = base + ((t + 1) & 1) * STAGE + so;
            size_t ka = gA + (size_t)(t + 1) * 32;
            size_t kb = gB + (size_t)(t + 1) * 32;
            CP16(sb,                 Ah + ka);  CP16(sb + 16,             Ah + ka + 8);
            CP16(sb + PLANE,         Al + ka);  CP16(sb + PLANE + 16,     Al + ka + 8);
            CP16(sb + 2 * PLANE,     Bh + kb);  CP16(sb + 2 * PLANE + 16, Bh + kb + 8);
            CP16(sb + 3 * PLANE,     Bl + kb);  CP16(sb + 3 * PLANE + 16, Bl + kb + 8);
            CP_COMMIT();
            CP_WAIT1();
        } else {
            CP_WAIT0();
        }
        __syncthreads();

        const uint32_t sb = base + (t & 1) * STAGE;
        #pragma unroll
        for (int kk = 0; kk < 32; kk += 16) {
            uint32_t ah[4][4], al[4][4], bh[4][2], bl[4][2];
            #pragma unroll
            for (int i = 0; i < 4; i++)
                ldm_x4(ah[i], sb + a_off + (uint32_t)i * (16 * RS) + kk * 2);
            #pragma unroll
            for (int i = 0; i < 4; i++)
                ldm_x4(al[i], sb + PLANE + a_off + (uint32_t)i * (16 * RS) + kk * 2);
            #pragma unroll
            for (int j = 0; j < 4; j++)
                ldm_x2(bh[j], sb + b_off + (uint32_t)j * (8 * RS) + kk * 2);
            #pragma unroll
            for (int j = 0; j < 4; j++)
                ldm_x2(bl[j], sb + PLANE + b_off + (uint32_t)j * (8 * RS) + kk * 2);

            #pragma unroll
            for (int i = 0; i < 4; i++)
                #pragma unroll
                for (int j = 0; j < 4; j++) {
                    mma16816(acc[i][j], ah[i], bh[j]);
                    mma16816(acc[i][j], ah[i], bl[j]);
                    mma16816(acc[i][j], al[i], bh[j]);
                }
        }
        __syncthreads();
    }

    // epilogue
    const int rbase = m0 + (wid & 1) * 64 + (lane >> 2);
    const int cbase = n0 + (wid >> 1) * 32 + (lane & 3) * 2;
    #pragma unroll
    for (int i = 0; i < 4; i++) {
        #pragma unroll
        for (int j = 0; j < 4; j++) {
            int rrow = rbase + i * 16;
            int col  = cbase + j * 8;
            float b0 = bias[col], b1 = bias[col + 1];
            float o0 = acc[i][j][0] + b0, o1 = acc[i][j][1] + b1;
            float o2 = acc[i][j][2] + b0, o3 = acc[i][j][3] + b1;
            size_t off0 = (size_t)rrow * Dn + col;
            size_t off1 = (size_t)(rrow + 8) * Dn + col;
            if (resid) {
                float2 r0 = *(const float2*)&resid[off0];
                float2 r1 = *(const float2*)&resid[off1];
                o0 += r0.x; o1 += r0.y; o2 += r1.x; o3 += r1.y;
            }
            if (Cf) {
                float2 w0 = {o0, o1}, w1 = {o2, o3};
                *(float2*)&Cf[off0] = w0;
                *(float2*)&Cf[off1] = w1;
            }
            if (Oh) {
                uint32_t h0, l0, h1, l1;
                split2(o0, o1, h0, l0);
                split2(o2, o3, h1, l1);
                ((uint32_t*)Oh)[off0 >> 1] = h0;
                ((uint32_t*)Ol)[off0 >> 1] = l0;
                ((uint32_t*)Oh)[off1 >> 1] = h1;
                ((uint32_t*)Ol)[off1 >> 1] = l1;
            }
        }
    }
}

// merged Q/K/V projections: blockIdx.z selects which
__global__ __launch_bounds__(256, 2) void qkv_gemm(
    const __nv_bfloat16* __restrict__ sh, const __nv_bfloat16* __restrict__ sl,
    const __nv_bfloat16* __restrict__ wqh, const __nv_bfloat16* __restrict__ wql,
    const __nv_bfloat16* __restrict__ wkh, const __nv_bfloat16* __restrict__ wkl,
    const __nv_bfloat16* __restrict__ wvh, const __nv_bfloat16* __restrict__ wvl,
    const float* __restrict__ bq, const float* __restrict__ bk,
    const float* __restrict__ bv,
    __nv_bfloat16* __restrict__ qh, __nv_bfloat16* __restrict__ ql,
    __nv_bfloat16* __restrict__ kh, __nv_bfloat16* __restrict__ kl,
    __nv_bfloat16* __restrict__ vh, __nv_bfloat16* __restrict__ vl)
{
    extern __shared__ __align__(128) char dsm[];
    const int z = blockIdx.z;
    const size_t actN = (size_t)Mn * Dn;
    const __nv_bfloat16* Ah = sh + (size_t)z * actN;
    const __nv_bfloat16* Al = sl + (size_t)z * actN;
    const __nv_bfloat16* Bh = (z == 0) ? wqh : (z == 1) ? wkh : wvh;
    const __nv_bfloat16* Bl = (z == 0) ? wql : (z == 1) ? wkl : wvl;
    const float* bias = (z == 0) ? bq : (z == 1) ? bk : bv;
    __nv_bfloat16* Oh = (z == 0) ? qh : (z == 1) ? kh : vh;
    __nv_bfloat16* Ol = (z == 0) ? ql : (z == 1) ? kl : vl;
    gemm_core(Ah, Al, Bh, Bl, bias, nullptr, nullptr, Oh, Ol, dsm);
}

// output projection + residual -> fp32
__global__ __launch_bounds__(256, 2) void o_gemm(
    const __nv_bfloat16* __restrict__ ch, const __nv_bfloat16* __restrict__ cl,
    const __nv_bfloat16* __restrict__ woh, const __nv_bfloat16* __restrict__ wol,
    const float* __restrict__ bo, const float* __restrict__ resid,
    float* __restrict__ y)
{
    extern __shared__ __align__(128) char dsm[];
    gemm_core(ch, cl, woh, wol, bo, resid, y, nullptr, nullptr, dsm);
}

// ============================================================
// Tensor-core attention, view-space [128 g][1024][64].
// CTA: 64 q-rows (4 warps x 16), streams 64-key tiles.
// k_mask staged per-tile (256B) in the cp.async pipeline ->
// smem/CTA 74.2KB -> 3 CTAs/SM.
// ============================================================
#define ARS 144u
#define APL 9216u
#define KMOFF 36864u
#define ASTG 37120u
#define ATT_SMEM (2 * 37120)

__global__ __launch_bounds__(128, 3) void attn_mma(
    const __nv_bfloat16* __restrict__ qh, const __nv_bfloat16* __restrict__ ql,
    const __nv_bfloat16* __restrict__ kh, const __nv_bfloat16* __restrict__ kl,
    const __nv_bfloat16* __restrict__ vh, const __nv_bfloat16* __restrict__ vl,
    const float* __restrict__ qm, const float* __restrict__ km,
    __nv_bfloat16* __restrict__ ch, __nv_bfloat16* __restrict__ cl)
{
    extern __shared__ __align__(128) char asmem[];
    const uint32_t base = smem_u32(asmem);
    const int tid = threadIdx.x;
    const int lane = tid & 31, wid = tid >> 5;
    const int g = blockIdx.y;
    const int q0 = blockIdx.x << 6;
    const int mb = g & 7;
    const size_t gbase = (size_t)g * (Ln * DH);
    const float* kmrow = km + mb * Ln;

    // Q tile into stage-0 smem
    #pragma unroll
    for (int i = 0; i < 8; i++) {
        int id = i * 128 + tid;
        int pl = id >> 9, r = (id >> 3) & 63, seg = id & 7;
        const __nv_bfloat16* src = (pl ? ql : qh) + gbase + (size_t)(q0 + r) * DH + seg * 8;
        CP16(base + (uint32_t)pl * APL + (uint32_t)r * ARS + (uint32_t)seg * 16, src);
    }
    CP_COMMIT();
    CP_WAIT0();
    __syncthreads();

    uint32_t qa_h[4][4], qa_l[4][4];
    {
        uint32_t ab = base + (uint32_t)(wid * 16 + (lane & 15)) * ARS
                    + (uint32_t)(lane >> 4) * 16;
        #pragma unroll
        for (int kb = 0; kb < 4; kb++) {
            ldm_x4(qa_h[kb], ab + kb * 32);
            ldm_x4(qa_l[kb], ab + APL + kb * 32);
        }
    }
    __syncthreads();

    const float qm0 = qm[mb * Ln + q0 + wid * 16 + (lane >> 2)];
    const float qm1 = qm[mb * Ln + q0 + wid * 16 + (lane >> 2) + 8];

    float o[8][4] = {};
    float den0 = 0.f, den1 = 0.f;

    // prologue: K/V tile 0 + km slice -> stage 0
    #pragma unroll
    for (int i = 0; i < 16; i++) {
        int id = i * 128 + tid;
        int pl = id >> 9, r = (id >> 3) & 63, seg = id & 7;
        const __nv_bfloat16* bp = (pl == 0) ? kh : (pl == 1) ? kl : (pl == 2) ? vh : vl;
        CP16(base + (uint32_t)pl * APL + (uint32_t)r * ARS + (uint32_t)seg * 16,
             bp + gbase + (size_t)r * DH + seg * 8);
    }
    if (tid < 16) CP16(base + KMOFF + (uint32_t)tid * 16, kmrow + tid * 4);
    CP_COMMIT();

    for (int t = 0; t < 16; t++) {
        if (t < 15) {
            uint32_t sb2 = base + (uint32_t)((t + 1) & 1) * ASTG;
            int k0n = (t + 1) << 6;
            #pragma unroll
            for (int i = 0; i < 16; i++) {
                int id = i * 128 + tid;
                int pl = id >> 9, r = (id >> 3) & 63, seg = id & 7;
                const __nv_bfloat16* bp = (pl == 0) ? kh : (pl == 1) ? kl : (pl == 2) ? vh : vl;
                CP16(sb2 + (uint32_t)pl * APL + (uint32_t)r * ARS + (uint32_t)seg * 16,
                     bp + gbase + (size_t)(k0n + r) * DH + seg * 8);
            }
            if (tid < 16) CP16(sb2 + KMOFF + (uint32_t)tid * 16, kmrow + k0n + tid * 4);
            CP_COMMIT();
            CP_WAIT1();
        } else {
            CP_WAIT0();
        }
        __syncthreads();

        const uint32_t sb = base + (uint32_t)(t & 1) * ASTG;

        // ---- S = Q K^T (3-term) ----
        float s[8][4];
        #pragma unroll
        for (int j = 0; j < 8; j++)
            #pragma unroll
            for (int c = 0; c < 4; c++) s[j][c] = 0.f;

        const uint32_t bb = sb + (uint32_t)(lane & 7) * ARS
                          + (uint32_t)((lane >> 3) & 1) * 16;
        #pragma unroll
        for (int j = 0; j < 8; j++) {
            #pragma unroll
            for (int kb = 0; kb < 4; kb++) {
                uint32_t bh2[2], bl2[2];
                ldm_x2(bh2, bb + (uint32_t)j * (8 * ARS) + kb * 32);
                ldm_x2(bl2, bb + APL + (uint32_t)j * (8 * ARS) + kb * 32);
                mma16816(s[j], qa_h[kb], bh2);
                mma16816(s[j], qa_h[kb], bl2);
                mma16816(s[j], qa_l[kb], bh2);
            }
        }

        // ---- mask + exp + den (km slice from stage smem) ----
        const float* kms = (const float*)(asmem + ((t & 1) ? ASTG : 0u) + KMOFF);
        float e[8][4];
        const int kcb = (lane & 3) << 1;
        #pragma unroll
        for (int j = 0; j < 8; j++) {
            float km0v = kms[kcb + j * 8];
            float km1v = kms[kcb + j * 8 + 1];
            e[j][0] = (qm0 * km0v == 0.f) ? 0.f : __expf(s[j][0] * 0.125f);
            e[j][1] = (qm0 * km1v == 0.f) ? 0.f : __expf(s[j][1] * 0.125f);
            e[j][2] = (qm1 * km0v == 0.f) ? 0.f : __expf(s[j][2] * 0.125f);
            e[j][3] = (qm1 * km1v == 0.f) ? 0.f : __expf(s[j][3] * 0.125f);
            den0 += e[j][0] + e[j][1];
            den1 += e[j][2] + e[j][3];
        }

        // ---- O += P V (3-term, P split in regs) ----
        const uint32_t vb = sb + 2 * APL + (uint32_t)(lane & 15) * ARS;
        #pragma unroll
        for (int tt = 0; tt < 4; tt++) {
            uint32_t ah2[4], al2[4];
            split2(e[2 * tt][0],     e[2 * tt][1],     ah2[0], al2[0]);
            split2(e[2 * tt][2],     e[2 * tt][3],     ah2[1], al2[1]);
            split2(e[2 * tt + 1][0], e[2 * tt + 1][1], ah2[2], al2[2]);
            split2(e[2 * tt + 1][2], e[2 * tt + 1][3], ah2[3], al2[3]);
            #pragma unroll
            for (int jd = 0; jd < 8; jd++) {
                uint32_t vh2[2], vl2[2];
                ldm_x2t(vh2, vb + (uint32_t)tt * (16 * ARS) + jd * 16);
                ldm_x2t(vl2, vb + APL + (uint32_t)tt * (16 * ARS) + jd * 16);
                mma16816(o[jd], ah2, vh2);
                mma16816(o[jd], ah2, vl2);
                mma16816(o[jd], al2, vh2);
            }
        }
        __syncthreads();
    }

    den0 += __shfl_xor_sync(0xffffffffu, den0, 1);
    den0 += __shfl_xor_sync(0xffffffffu, den0, 2);
    den1 += __shfl_xor_sync(0xffffffffu, den1, 1);
    den1 += __shfl_xor_sync(0xffffffffu, den1, 2);
    const float i0 = 1.f / fmaxf(den0, 2e-15f);
    const float i1 = 1.f / fmaxf(den1, 2e-15f);

    const int row0 = q0 + wid * 16 + (lane >> 2);
    const int colb = (lane & 3) << 1;
    #pragma unroll
    for (int jd = 0; jd < 8; jd++) {
        int col = jd * 8 + colb;
        float v0 = o[jd][0] * i0, v1 = o[jd][1] * i0;
        float v2 = o[jd][2] * i1, v3 = o[jd][3] * i1;
        size_t off0 = gbase + (size_t)row0 * DH + col;
        size_t off1 = off0 + 8 * DH;
        uint32_t h0, l0, h1, l1;
        split2(v0, v1, h0, l0);
        split2(v2, v3, h1, l1);
        ((uint32_t*)ch)[off0 >> 1] = h0;
        ((uint32_t*)cl)[off0 >> 1] = l0;
        ((uint32_t*)ch)[off1 >> 1] = h1;
        ((uint32_t*)cl)[off1 >> 1] = l1;
    }
}

// ============================================================
// LayerNorm
// ============================================================
__global__ __launch_bounds__(256) void ln_kernel(
    const float* __restrict__ y, const float* __restrict__ gamma,
    const float* __restrict__ beta, float* __restrict__ out)
{
    __shared__ float red[8];
    int row = blockIdx.x, tid = threadIdx.x;
    float4 v = ((const float4*)(y + (size_t)row * Dn))[tid];

    float s = v.x + v.y + v.z + v.w;
    #pragma unroll
    for (int o = 16; o; o >>= 1) s += __shfl_xor_sync(0xffffffffu, s, o);
    if ((tid & 31) == 0) red[tid >> 5] = s;
    __syncthreads();
    if (tid < 32) {
        float t = (tid < 8) ? red[tid] : 0.f;
        #pragma unroll
        for (int o = 4; o; o >>= 1) t += __shfl_xor_sync(0xffffffffu, t, o);
        if (tid == 0) red[0] = t;
    }
    __syncthreads();
    float mean = red[0] * (1.f / Dn);
    __syncthreads();

    float dx = v.x - mean, dy = v.y - mean, dz = v.z - mean, dw = v.w - mean;
    float sq = dx * dx + dy * dy + dz * dz + dw * dw;
    #pragma unroll
    for (int o = 16; o; o >>= 1) sq += __shfl_xor_sync(0xffffffffu, sq, o);
    if ((tid & 31) == 0) red[tid >> 5] = sq;
    __syncthreads();
    if (tid < 32) {
        float t = (tid < 8) ? red[tid] : 0.f;
        #pragma unroll
        for (int o = 4; o; o >>= 1) t += __shfl_xor_sync(0xffffffffu, t, o);
        if (tid == 0) red[0] = t;
    }
    __syncthreads();
    float rstd = rsqrtf(red[0] * (1.f / Dn) + 1e-5f);

    float4 g4 = ((const float4*)gamma)[tid];
    float4 b4 = ((const float4*)beta)[tid];
    float4 o4;
    o4.x = dx * rstd * g4.x + b4.x;
    o4.y = dy * rstd * g4.y + b4.y;
    o4.z = dz * rstd * g4.z + b4.z;
    o4.w = dw * rstd * g4.w + b4.w;
    ((float4*)(out + (size_t)row * Dn))[tid] = o4;
}

// ============================================================
extern "C" void kernel_launch(void* const* d_in, const int* in_sizes, int n_in,
                              void* d_out, int out_size)
{
    const float* query  = (const float*)d_in[0];
    const float* key_   = (const float*)d_in[1];
    const float* value  = (const float*)d_in[2];
    const float* q_mask = (const float*)d_in[3];
    const float* k_mask = (const float*)d_in[4];
    const float* Wq = (const float*)d_in[5];
    const float* bq = (const float*)d_in[6];
    const float* Wk = (const float*)d_in[7];
    const float* bk = (const float*)d_in[8];
    const float* Wv = (const float*)d_in[9];
    const float* bv = (const float*)d_in[10];
    const float* Wo = (const float*)d_in[11];
    const float* bo = (const float*)d_in[12];
    const float* gamma = (const float*)d_in[13];
    const float* beta  = (const float*)d_in[14];

    float* y;
    cudaGetSymbolAddress((void**)&y, g_y);

    __nv_bfloat16 *sh, *sl, *qh, *ql, *kh, *kl, *vh, *vl, *ch, *cl;
    __nv_bfloat16 *wqh, *wql, *wkh, *wkl, *wvh, *wvl, *woh, *wol;
    cudaGetSymbolAddress((void**)&sh, g_sh);  cudaGetSymbolAddress((void**)&sl, g_sl);
    cudaGetSymbolAddress((void**)&qh, g_qh);  cudaGetSymbolAddress((void**)&ql, g_ql);
    cudaGetSymbolAddress((void**)&kh, g_kh);  cudaGetSymbolAddress((void**)&kl, g_kl);
    cudaGetSymbolAddress((void**)&vh, g_vh);  cudaGetSymbolAddress((void**)&vl, g_vl);
    cudaGetSymbolAddress((void**)&ch, g_ch);  cudaGetSymbolAddress((void**)&cl, g_cl);
    cudaGetSymbolAddress((void**)&wqh, g_wqh); cudaGetSymbolAddress((void**)&wql, g_wql);
    cudaGetSymbolAddress((void**)&wkh, g_wkh); cudaGetSymbolAddress((void**)&wkl, g_wkl);
    cudaGetSymbolAddress((void**)&wvh, g_wvh); cudaGetSymbolAddress((void**)&wvl, g_wvl);
    cudaGetSymbolAddress((void**)&woh, g_woh); cudaGetSymbolAddress((void**)&wol, g_wol);

    cudaFuncSetAttribute(qkv_gemm, cudaFuncAttributeMaxDynamicSharedMemorySize, GM_SMEM);
    cudaFuncSetAttribute(o_gemm,   cudaFuncAttributeMaxDynamicSharedMemorySize, GM_SMEM);
    cudaFuncSetAttribute(attn_mma, cudaFuncAttributeMaxDynamicSharedMemorySize, ATT_SMEM);

    const int n4_act = (Mn * Dn) / 4;
    const int n4_w   = (Dn * Dn) / 4;

    // 1: all weight splits
    wsplit_all<<<dim3(n4_w / 256, 4), 256>>>(Wq, Wk, Wv, Wo,
        wqh, wql, wkh, wkl, wvh, wvl, woh, wol);
    // 2: all activation splits
    asplit3<<<dim3(n4_act / 256, 3), 256>>>(query, key_, value, sh, sl);

    // 3: merged Q/K/V projections
    qkv_gemm<<<dim3(Dn / 128, Mn / 128, 3), 256, GM_SMEM>>>(
        sh, sl, wqh, wql, wkh, wkl, wvh, wvl, bq, bk, bv,
        qh, ql, kh, kl, vh, vl);

    // 4: attention
    attn_mma<<<dim3(Ln / 64, Bn * Hn), 128, ATT_SMEM>>>(
        qh, ql, kh, kl, vh, vl, q_mask, k_mask, ch, cl);

    // 5: output projection + residual
    o_gemm<<<dim3(Dn / 128, Mn / 128), 256, GM_SMEM>>>(
        ch, cl, woh, wol, bo, query, y);

    // 6: layernorm
    ln_kernel<<<Mn, 256>>>(y, gamma, beta, (float*)d_out);
}